// round 6
// baseline (speedup 1.0000x reference)
#include <cuda_runtime.h>
#include <cuda_bf16.h>
#include <math.h>
#include <stdint.h>

// Problem constants
#define BB 2
#define SS 2048
#define EE 1024
#define HH 16
#define DD 64
#define MM (BB * SS)   // 4096 rows for projection GEMMs

// ---------------- scratch (device globals; no allocations allowed) ----------
__device__ float g_qp[BB * SS * EE];   // Q projected, [B,S,E]
__device__ float g_kp[BB * SS * EE];   // K projected
__device__ float g_vp[BB * SS * EE];   // V projected
__device__ float g_at[BB * SS * EE];   // attention output (concat), [B,S,E]

// ======================= helpers ============================================
__device__ __forceinline__ uint32_t smem_u32(const void* p) {
    uint32_t a;
    asm("{ .reg .u64 t; cvta.to.shared.u64 t, %1; cvt.u32.u64 %0, t; }"
        : "=r"(a) : "l"(p));
    return a;
}
__device__ __forceinline__ void cp16(uint32_t dst, const void* src) {
    asm volatile("cp.async.cg.shared.global [%0], [%1], 16;" :: "r"(dst), "l"(src));
}
#define CP_COMMIT() asm volatile("cp.async.commit_group;" ::: "memory")
#define CP_WAIT0()  asm volatile("cp.async.wait_group 0;" ::: "memory")
#define CP_WAIT1()  asm volatile("cp.async.wait_group 1;" ::: "memory")

// tf32 round-to-nearest conversion (keeps value as f32 bits with low mantissa 0)
__device__ __forceinline__ uint32_t f2tf(float x) {
    uint32_t r;
    asm("cvt.rna.tf32.f32 %0, %1;" : "=r"(r) : "f"(x));
    return r;
}
// split x into hi (tf32) + lo (tf32 of residual)
__device__ __forceinline__ void tf32_split(float x, uint32_t& hi, uint32_t& lo) {
    hi = f2tf(x);
    lo = f2tf(x - __uint_as_float(hi));
}

__device__ __forceinline__ void mma_tf32(float* d, const uint32_t* a, const uint32_t* b) {
    asm volatile(
        "mma.sync.aligned.m16n8k8.row.col.f32.tf32.tf32.f32 "
        "{%0,%1,%2,%3}, {%4,%5,%6,%7}, {%8,%9}, {%0,%1,%2,%3};"
        : "+f"(d[0]), "+f"(d[1]), "+f"(d[2]), "+f"(d[3])
        : "r"(a[0]), "r"(a[1]), "r"(a[2]), "r"(a[3]), "r"(b[0]), "r"(b[1]));
}

// ======================= tf32 mma.sync GEMM (unchanged from R5) =============
#define SA 36
#define SB 132
#define A_BUF_F (128 * SA)
#define B_BUF_F (32 * SB)
#define GEMM_SMEM_F (2 * A_BUF_F + 2 * B_BUF_F)
#define GEMM_SMEM_B (GEMM_SMEM_F * 4)

__global__ __launch_bounds__(256, 1)
void gemm_tf32_mma(const float* __restrict__ A, const float* __restrict__ W,
                   const float* __restrict__ bias, float* __restrict__ C)
{
    extern __shared__ float smem[];
    float* As[2] = {smem, smem + A_BUF_F};
    float* Bs[2] = {smem + 2 * A_BUF_F, smem + 2 * A_BUF_F + B_BUF_F};
    const uint32_t sb0 = smem_u32(smem);

    const int tid = threadIdx.x;
    const int lane = tid & 31;
    const int wid = tid >> 5;
    const int warpM = wid >> 2;
    const int warpN = wid & 3;
    const int bm = blockIdx.y * 128;
    const int bn = blockIdx.x * 128;

    const int lg = lane >> 2;
    const int lt = lane & 3;

    float acc[4][4][4];
#pragma unroll
    for (int mi = 0; mi < 4; mi++)
#pragma unroll
        for (int ni = 0; ni < 4; ni++)
#pragma unroll
            for (int r = 0; r < 4; r++) acc[mi][ni][r] = 0.0f;

    auto load_tiles = [&](int buf, int it) {
        const float* Ab = A + (size_t)bm * EE + it * 32;
        const float* Wb = W + (size_t)(it * 32) * EE + bn;
        const uint32_t sa = sb0 + (uint32_t)((As[buf] - smem) * 4);
        const uint32_t sw = sb0 + (uint32_t)((Bs[buf] - smem) * 4);
#pragma unroll
        for (int i = 0; i < 4; i++) {
            int cid = tid + i * 256;
            int row = cid >> 3, c4 = (cid & 7) * 4;
            cp16(sa + (uint32_t)(row * SA + c4) * 4, Ab + (size_t)row * EE + c4);
        }
#pragma unroll
        for (int i = 0; i < 4; i++) {
            int cid = tid + i * 256;
            int kk = cid >> 5, c4 = (cid & 31) * 4;
            cp16(sw + (uint32_t)(kk * SB + c4) * 4, Wb + (size_t)kk * EE + c4);
        }
    };

    load_tiles(0, 0); CP_COMMIT();
    load_tiles(1, 1); CP_COMMIT();

    for (int it = 0; it < 32; it++) {
        if (it == 31) { CP_WAIT0(); } else { CP_WAIT1(); }
        __syncthreads();

        const float* A_ = As[it & 1];
        const float* B_ = Bs[it & 1];

#pragma unroll
        for (int ks = 0; ks < 4; ks++) {
            const int kb = ks * 8;
            uint32_t ah[4][4], al[4][4];
#pragma unroll
            for (int mi = 0; mi < 4; mi++) {
                const int r0 = warpM * 64 + mi * 16 + lg;
                const int kk = kb + lt;
                tf32_split(A_[r0 * SA + kk],        ah[mi][0], al[mi][0]);
                tf32_split(A_[(r0 + 8) * SA + kk],  ah[mi][1], al[mi][1]);
                tf32_split(A_[r0 * SA + kk + 4],    ah[mi][2], al[mi][2]);
                tf32_split(A_[(r0 + 8) * SA + kk + 4], ah[mi][3], al[mi][3]);
            }
            uint32_t bh[4][2], bl[4][2];
#pragma unroll
            for (int ni = 0; ni < 4; ni++) {
                const int nn = warpN * 32 + ni * 8 + lg;
                const int kk = kb + lt;
                tf32_split(B_[kk * SB + nn],       bh[ni][0], bl[ni][0]);
                tf32_split(B_[(kk + 4) * SB + nn], bh[ni][1], bl[ni][1]);
            }
#pragma unroll
            for (int mi = 0; mi < 4; mi++)
#pragma unroll
                for (int ni = 0; ni < 4; ni++) {
                    mma_tf32(acc[mi][ni], ah[mi], bh[ni]);
                    mma_tf32(acc[mi][ni], al[mi], bh[ni]);
                    mma_tf32(acc[mi][ni], ah[mi], bl[ni]);
                }
        }
        __syncthreads();
        if (it + 2 < 32) { load_tiles(it & 1, it + 2); CP_COMMIT(); }
    }

#pragma unroll
    for (int mi = 0; mi < 4; mi++) {
        const int row0 = bm + warpM * 64 + mi * 16 + lg;
#pragma unroll
        for (int ni = 0; ni < 4; ni++) {
            const int col = bn + warpN * 32 + ni * 8 + lt * 2;
            const float b0 = bias[col], b1 = bias[col + 1];
            float2 v0 = make_float2(acc[mi][ni][0] + b0, acc[mi][ni][1] + b1);
            float2 v1 = make_float2(acc[mi][ni][2] + b0, acc[mi][ni][3] + b1);
            *(float2*)&C[(size_t)row0 * EE + col] = v0;
            *(float2*)&C[(size_t)(row0 + 8) * EE + col] = v1;
        }
    }
}

// ================= Flash attention (causal) with tf32 mma.sync ==============
// BQ=128 q rows per CTA, BK=64 keys per iter, 256 threads = 8 warps.
// Warp w owns q-rows [w*16, w*16+16) x all 64 key cols -> row softmax is
// warp-local (quad shfl only). P goes through smem to become an A-operand.
// 3-term tf32 split on both QK^T and PV for fp32-level accuracy.
#define FQ 128
#define FK 64
#define QS_STR 68
#define PS_STR 68
#define KS_STR 68
#define VS_STR 72
#define OFF_P (FQ * QS_STR)
#define OFF_K (OFF_P + FQ * PS_STR)
#define OFF_V (OFF_K + FK * KS_STR)
#define FLASH2_SMEM_F (OFF_V + FK * VS_STR)
#define FLASH2_SMEM_B (FLASH2_SMEM_F * 4)   // 105472 bytes

__global__ __launch_bounds__(256, 1)
void flash_mma_kernel(const float* __restrict__ Qp,
                      const float* __restrict__ Kp,
                      const float* __restrict__ Vp,
                      float* __restrict__ Out)
{
    extern __shared__ float sf[];
    float* Qs = sf;
    float* Ps = sf + OFF_P;
    float* Ks = sf + OFF_K;
    float* Vs = sf + OFF_V;

    const int tid = threadIdx.x;
    const int lane = tid & 31;
    const int w = tid >> 5;
    const int lg = lane >> 2;
    const int lt = lane & 3;
    const int qt = (gridDim.x - 1) - blockIdx.x;   // big CTAs first
    const int h = blockIdx.y;
    const int b = blockIdx.z;
    const int qbase = qt * FQ;
    const size_t head = (size_t)h * DD;

    // load Q tile, pre-scaled by 1/sqrt(D)=0.125
    for (int i = tid; i < FQ * 16; i += 256) {
        int row = i >> 4, c4 = (i & 15) * 4;
        float4 q4 = *(const float4*)&Qp[((size_t)(b * SS + qbase + row)) * EE + head + c4];
        q4.x *= 0.125f; q4.y *= 0.125f; q4.z *= 0.125f; q4.w *= 0.125f;
        *(float4*)&Qs[row * QS_STR + c4] = q4;
    }

    float oacc[8][4];
#pragma unroll
    for (int ni = 0; ni < 8; ni++)
#pragma unroll
        for (int r = 0; r < 4; r++) oacc[ni][r] = 0.0f;
    float m0 = -1e30f, m1 = -1e30f, l0 = 0.0f, l1 = 0.0f;

    const int r0 = w * 16 + lg;
    const int nkt = (qbase + FQ) / FK;   // 2*qt + 2 key tiles

    for (int kt = 0; kt < nkt; kt++) {
        const int kbase = kt * FK;
        __syncthreads();   // previous PV reads of Ps/Vs done before overwrite
        for (int i = tid; i < FK * 16; i += 256) {
            int row = i >> 4, c4 = (i & 15) * 4;
            const size_t g = ((size_t)(b * SS + kbase + row)) * EE + head + c4;
            *(float4*)&Ks[row * KS_STR + c4] = *(const float4*)&Kp[g];
            *(float4*)&Vs[row * VS_STR + c4] = *(const float4*)&Vp[g];
        }
        __syncthreads();

        // ---- S = Q @ K^T (3xTF32)
        float sacc[8][4];
#pragma unroll
        for (int ni = 0; ni < 8; ni++)
#pragma unroll
            for (int r = 0; r < 4; r++) sacc[ni][r] = 0.0f;

#pragma unroll
        for (int ks = 0; ks < 8; ks++) {
            const int kk = ks * 8 + lt;
            uint32_t ah[4], al[4];
            tf32_split(Qs[r0 * QS_STR + kk],           ah[0], al[0]);
            tf32_split(Qs[(r0 + 8) * QS_STR + kk],     ah[1], al[1]);
            tf32_split(Qs[r0 * QS_STR + kk + 4],       ah[2], al[2]);
            tf32_split(Qs[(r0 + 8) * QS_STR + kk + 4], ah[3], al[3]);
#pragma unroll
            for (int ni = 0; ni < 8; ni++) {
                uint32_t bh[2], bl[2];
                tf32_split(Ks[(ni * 8 + lg) * KS_STR + kk],     bh[0], bl[0]);
                tf32_split(Ks[(ni * 8 + lg) * KS_STR + kk + 4], bh[1], bl[1]);
                mma_tf32(sacc[ni], ah, bh);
                mma_tf32(sacc[ni], al, bh);
                mma_tf32(sacc[ni], ah, bl);
            }
        }

        // ---- causal mask (only near-diagonal tiles)
        if (kt >= 2 * qt) {
            const int grow0 = qbase + r0;
#pragma unroll
            for (int ni = 0; ni < 8; ni++) {
                const int c0 = kbase + ni * 8 + lt * 2;
                if (c0 > grow0)     sacc[ni][0] = -1e30f;
                if (c0 + 1 > grow0) sacc[ni][1] = -1e30f;
                if (c0 > grow0 + 8)     sacc[ni][2] = -1e30f;
                if (c0 + 1 > grow0 + 8) sacc[ni][3] = -1e30f;
            }
        }

        // ---- online softmax (rows lg and lg+8; quad = lanes sharing lg)
        float rmax0 = -1e30f, rmax1 = -1e30f;
#pragma unroll
        for (int ni = 0; ni < 8; ni++) {
            rmax0 = fmaxf(rmax0, fmaxf(sacc[ni][0], sacc[ni][1]));
            rmax1 = fmaxf(rmax1, fmaxf(sacc[ni][2], sacc[ni][3]));
        }
        rmax0 = fmaxf(rmax0, __shfl_xor_sync(0xffffffffu, rmax0, 1));
        rmax0 = fmaxf(rmax0, __shfl_xor_sync(0xffffffffu, rmax0, 2));
        rmax1 = fmaxf(rmax1, __shfl_xor_sync(0xffffffffu, rmax1, 1));
        rmax1 = fmaxf(rmax1, __shfl_xor_sync(0xffffffffu, rmax1, 2));

        const float newm0 = fmaxf(m0, rmax0);
        const float newm1 = fmaxf(m1, rmax1);
        const float alpha0 = __expf(m0 - newm0);
        const float alpha1 = __expf(m1 - newm1);
        m0 = newm0; m1 = newm1;

        float rsum0 = 0.0f, rsum1 = 0.0f;
#pragma unroll
        for (int ni = 0; ni < 8; ni++) {
            sacc[ni][0] = __expf(sacc[ni][0] - m0);
            sacc[ni][1] = __expf(sacc[ni][1] - m0);
            sacc[ni][2] = __expf(sacc[ni][2] - m1);
            sacc[ni][3] = __expf(sacc[ni][3] - m1);
            rsum0 += sacc[ni][0] + sacc[ni][1];
            rsum1 += sacc[ni][2] + sacc[ni][3];
        }
        rsum0 += __shfl_xor_sync(0xffffffffu, rsum0, 1);
        rsum0 += __shfl_xor_sync(0xffffffffu, rsum0, 2);
        rsum1 += __shfl_xor_sync(0xffffffffu, rsum1, 1);
        rsum1 += __shfl_xor_sync(0xffffffffu, rsum1, 2);
        l0 = l0 * alpha0 + rsum0;
        l1 = l1 * alpha1 + rsum1;

#pragma unroll
        for (int ni = 0; ni < 8; ni++) {
            oacc[ni][0] *= alpha0;
            oacc[ni][1] *= alpha0;
            oacc[ni][2] *= alpha1;
            oacc[ni][3] *= alpha1;
            *(float2*)&Ps[r0 * PS_STR + ni * 8 + lt * 2] =
                make_float2(sacc[ni][0], sacc[ni][1]);
            *(float2*)&Ps[(r0 + 8) * PS_STR + ni * 8 + lt * 2] =
                make_float2(sacc[ni][2], sacc[ni][3]);
        }
        __syncwarp();   // warp reads only its own P rows

        // ---- O += P @ V (3xTF32)
#pragma unroll
        for (int ks = 0; ks < 8; ks++) {
            const int kk = ks * 8 + lt;
            uint32_t ah[4], al[4];
            tf32_split(Ps[r0 * PS_STR + kk],           ah[0], al[0]);
            tf32_split(Ps[(r0 + 8) * PS_STR + kk],     ah[1], al[1]);
            tf32_split(Ps[r0 * PS_STR + kk + 4],       ah[2], al[2]);
            tf32_split(Ps[(r0 + 8) * PS_STR + kk + 4], ah[3], al[3]);
#pragma unroll
            for (int ni = 0; ni < 8; ni++) {
                uint32_t bh[2], bl[2];
                tf32_split(Vs[kk * VS_STR + ni * 8 + lg],       bh[0], bl[0]);
                tf32_split(Vs[(kk + 4) * VS_STR + ni * 8 + lg], bh[1], bl[1]);
                mma_tf32(oacc[ni], ah, bh);
                mma_tf32(oacc[ni], al, bh);
                mma_tf32(oacc[ni], ah, bl);
            }
        }
    }

    // ---- epilogue
    const float inv0 = 1.0f / l0;
    const float inv1 = 1.0f / l1;
    const int grow = qbase + r0;
#pragma unroll
    for (int ni = 0; ni < 8; ni++) {
        const size_t col = head + ni * 8 + lt * 2;
        *(float2*)&Out[((size_t)(b * SS + grow)) * EE + col] =
            make_float2(oacc[ni][0] * inv0, oacc[ni][1] * inv0);
        *(float2*)&Out[((size_t)(b * SS + grow + 8)) * EE + col] =
            make_float2(oacc[ni][2] * inv1, oacc[ni][3] * inv1);
    }
}

// ---------------- launch ----------------------------------------------------
extern "C" void kernel_launch(void* const* d_in, const int* in_sizes, int n_in,
                              void* d_out, int out_size)
{
    const float* q  = (const float*)d_in[0];
    const float* k  = (const float*)d_in[1];
    const float* v  = (const float*)d_in[2];
    const float* Wq = (const float*)d_in[3];
    const float* bq = (const float*)d_in[4];
    const float* Wk = (const float*)d_in[5];
    const float* bk = (const float*)d_in[6];
    const float* Wv = (const float*)d_in[7];
    const float* bv = (const float*)d_in[8];
    const float* Wo = (const float*)d_in[9];
    const float* bo = (const float*)d_in[10];
    float* out = (float*)d_out;

    float* qp; cudaGetSymbolAddress((void**)&qp, g_qp);
    float* kp; cudaGetSymbolAddress((void**)&kp, g_kp);
    float* vp; cudaGetSymbolAddress((void**)&vp, g_vp);
    float* at; cudaGetSymbolAddress((void**)&at, g_at);

    cudaFuncSetAttribute(gemm_tf32_mma,
                         cudaFuncAttributeMaxDynamicSharedMemorySize,
                         GEMM_SMEM_B);
    cudaFuncSetAttribute(flash_mma_kernel,
                         cudaFuncAttributeMaxDynamicSharedMemorySize,
                         FLASH2_SMEM_B);

    dim3 ggrid(EE / 128, MM / 128);   // (8, 32)
    gemm_tf32_mma<<<ggrid, 256, GEMM_SMEM_B>>>(q, Wq, bq, qp);
    gemm_tf32_mma<<<ggrid, 256, GEMM_SMEM_B>>>(k, Wk, bk, kp);
    gemm_tf32_mma<<<ggrid, 256, GEMM_SMEM_B>>>(v, Wv, bv, vp);

    dim3 fa_grid(SS / FQ, HH, BB);    // (16, 16, 2)
    flash_mma_kernel<<<fa_grid, 256, FLASH2_SMEM_B>>>(qp, kp, vp, at);

    gemm_tf32_mma<<<ggrid, 256, GEMM_SMEM_B>>>(at, Wo, bo, out);
}

// round 7
// speedup vs baseline: 1.6169x; 1.6169x over previous
#include <cuda_runtime.h>
#include <cuda_bf16.h>
#include <math.h>
#include <stdint.h>

// Problem constants
#define BB 2
#define SS 2048
#define EE 1024
#define HH 16
#define DD 64
#define MM (BB * SS)   // 4096 rows for projection GEMMs

// ---------------- scratch (device globals; no allocations allowed) ----------
__device__ float g_qp[BB * SS * EE];   // Q projected, [B,S,E]
__device__ float g_kp[BB * SS * EE];   // K projected
__device__ float g_vp[BB * SS * EE];   // V projected
__device__ float g_at[BB * SS * EE];   // attention output (concat), [B,S,E]

// ======================= helpers ============================================
__device__ __forceinline__ uint32_t smem_u32(const void* p) {
    uint32_t a;
    asm("{ .reg .u64 t; cvta.to.shared.u64 t, %1; cvt.u32.u64 %0, t; }"
        : "=r"(a) : "l"(p));
    return a;
}
__device__ __forceinline__ void cp16(uint32_t dst, const void* src) {
    asm volatile("cp.async.cg.shared.global [%0], [%1], 16;" :: "r"(dst), "l"(src));
}
#define CP_COMMIT() asm volatile("cp.async.commit_group;" ::: "memory")
#define CP_WAIT0()  asm volatile("cp.async.wait_group 0;" ::: "memory")
#define CP_WAIT1()  asm volatile("cp.async.wait_group 1;" ::: "memory")

// tf32 round-to-nearest conversion
__device__ __forceinline__ uint32_t f2tf(float x) {
    uint32_t r;
    asm("cvt.rna.tf32.f32 %0, %1;" : "=r"(r) : "f"(x));
    return r;
}
__device__ __forceinline__ void tf32_split(float x, uint32_t& hi, uint32_t& lo) {
    hi = f2tf(x);
    lo = f2tf(x - __uint_as_float(hi));
}

__device__ __forceinline__ void mma_tf32(float* d, const uint32_t* a, const uint32_t* b) {
    asm volatile(
        "mma.sync.aligned.m16n8k8.row.col.f32.tf32.tf32.f32 "
        "{%0,%1,%2,%3}, {%4,%5,%6,%7}, {%8,%9}, {%0,%1,%2,%3};"
        : "+f"(d[0]), "+f"(d[1]), "+f"(d[2]), "+f"(d[3])
        : "r"(a[0]), "r"(a[1]), "r"(a[2]), "r"(a[3]), "r"(b[0]), "r"(b[1]));
}

// ======================= tf32 mma.sync GEMM (R5, unchanged) =================
#define SA 36
#define SB 132
#define A_BUF_F (128 * SA)
#define B_BUF_F (32 * SB)
#define GEMM_SMEM_F (2 * A_BUF_F + 2 * B_BUF_F)
#define GEMM_SMEM_B (GEMM_SMEM_F * 4)

__global__ __launch_bounds__(256, 1)
void gemm_tf32_mma(const float* __restrict__ A, const float* __restrict__ W,
                   const float* __restrict__ bias, float* __restrict__ C)
{
    extern __shared__ float smem[];
    float* As[2] = {smem, smem + A_BUF_F};
    float* Bs[2] = {smem + 2 * A_BUF_F, smem + 2 * A_BUF_F + B_BUF_F};
    const uint32_t sb0 = smem_u32(smem);

    const int tid = threadIdx.x;
    const int lane = tid & 31;
    const int wid = tid >> 5;
    const int warpM = wid >> 2;
    const int warpN = wid & 3;
    const int bm = blockIdx.y * 128;
    const int bn = blockIdx.x * 128;

    const int lg = lane >> 2;
    const int lt = lane & 3;

    float acc[4][4][4];
#pragma unroll
    for (int mi = 0; mi < 4; mi++)
#pragma unroll
        for (int ni = 0; ni < 4; ni++)
#pragma unroll
            for (int r = 0; r < 4; r++) acc[mi][ni][r] = 0.0f;

    auto load_tiles = [&](int buf, int it) {
        const float* Ab = A + (size_t)bm * EE + it * 32;
        const float* Wb = W + (size_t)(it * 32) * EE + bn;
        const uint32_t sa = sb0 + (uint32_t)((As[buf] - smem) * 4);
        const uint32_t sw = sb0 + (uint32_t)((Bs[buf] - smem) * 4);
#pragma unroll
        for (int i = 0; i < 4; i++) {
            int cid = tid + i * 256;
            int row = cid >> 3, c4 = (cid & 7) * 4;
            cp16(sa + (uint32_t)(row * SA + c4) * 4, Ab + (size_t)row * EE + c4);
        }
#pragma unroll
        for (int i = 0; i < 4; i++) {
            int cid = tid + i * 256;
            int kk = cid >> 5, c4 = (cid & 31) * 4;
            cp16(sw + (uint32_t)(kk * SB + c4) * 4, Wb + (size_t)kk * EE + c4);
        }
    };

    load_tiles(0, 0); CP_COMMIT();
    load_tiles(1, 1); CP_COMMIT();

    for (int it = 0; it < 32; it++) {
        if (it == 31) { CP_WAIT0(); } else { CP_WAIT1(); }
        __syncthreads();

        const float* A_ = As[it & 1];
        const float* B_ = Bs[it & 1];

#pragma unroll
        for (int ks = 0; ks < 4; ks++) {
            const int kb = ks * 8;
            uint32_t ah[4][4], al[4][4];
#pragma unroll
            for (int mi = 0; mi < 4; mi++) {
                const int r0 = warpM * 64 + mi * 16 + lg;
                const int kk = kb + lt;
                tf32_split(A_[r0 * SA + kk],        ah[mi][0], al[mi][0]);
                tf32_split(A_[(r0 + 8) * SA + kk],  ah[mi][1], al[mi][1]);
                tf32_split(A_[r0 * SA + kk + 4],    ah[mi][2], al[mi][2]);
                tf32_split(A_[(r0 + 8) * SA + kk + 4], ah[mi][3], al[mi][3]);
            }
            uint32_t bh[4][2], bl[4][2];
#pragma unroll
            for (int ni = 0; ni < 4; ni++) {
                const int nn = warpN * 32 + ni * 8 + lg;
                const int kk = kb + lt;
                tf32_split(B_[kk * SB + nn],       bh[ni][0], bl[ni][0]);
                tf32_split(B_[(kk + 4) * SB + nn], bh[ni][1], bl[ni][1]);
            }
#pragma unroll
            for (int mi = 0; mi < 4; mi++)
#pragma unroll
                for (int ni = 0; ni < 4; ni++) {
                    mma_tf32(acc[mi][ni], ah[mi], bh[ni]);
                    mma_tf32(acc[mi][ni], al[mi], bh[ni]);
                    mma_tf32(acc[mi][ni], ah[mi], bl[ni]);
                }
        }
        __syncthreads();
        if (it + 2 < 32) { load_tiles(it & 1, it + 2); CP_COMMIT(); }
    }

#pragma unroll
    for (int mi = 0; mi < 4; mi++) {
        const int row0 = bm + warpM * 64 + mi * 16 + lg;
#pragma unroll
        for (int ni = 0; ni < 4; ni++) {
            const int col = bn + warpN * 32 + ni * 8 + lt * 2;
            const float b0 = bias[col], b1 = bias[col + 1];
            float2 v0 = make_float2(acc[mi][ni][0] + b0, acc[mi][ni][1] + b1);
            float2 v1 = make_float2(acc[mi][ni][2] + b0, acc[mi][ni][3] + b1);
            *(float2*)&C[(size_t)row0 * EE + col] = v0;
            *(float2*)&C[(size_t)(row0 + 8) * EE + col] = v1;
        }
    }
}

// ================= Flash attention (causal), tf32 mma, deduped splits =======
// FQ=128 q rows/CTA, FK=64 keys/iter, 256 threads = 8 warps; warp w owns
// q-rows [w*16, w*16+16) x all 64 cols. Q split once into registers; K/V split
// once per tile at load; P split once at store. Mainloop = LDS + HMMA only.
#define FQ 128
#define FK 64
#define QR_STR 68
#define P_STR 68
#define K_STR 68
#define V_STR 72
#define OFF_PHI (FQ * QR_STR)              // 8704
#define OFF_PLO (OFF_PHI + FQ * P_STR)     // 17408
#define OFF_KHI (OFF_PLO + FQ * P_STR)     // 26112
#define OFF_KLO (OFF_KHI + FK * K_STR)     // 30464
#define OFF_VHI (OFF_KLO + FK * K_STR)     // 34816
#define OFF_VLO (OFF_VHI + FK * V_STR)     // 39424
#define FLASH3_SMEM_F (OFF_VLO + FK * V_STR)   // 44032 floats
#define FLASH3_SMEM_B (FLASH3_SMEM_F * 4)      // 176128 bytes

__global__ __launch_bounds__(256, 1)
void flash_mma_kernel(const float* __restrict__ Qp,
                      const float* __restrict__ Kp,
                      const float* __restrict__ Vp,
                      float* __restrict__ Out)
{
    extern __shared__ float sf[];
    float* Qr  = sf;             // raw Q (only used before mainloop)
    float* Phi = sf + OFF_PHI;
    float* Plo = sf + OFF_PLO;
    float* Khi = sf + OFF_KHI;
    float* Klo = sf + OFF_KLO;
    float* Vhi = sf + OFF_VHI;
    float* Vlo = sf + OFF_VLO;

    const int tid = threadIdx.x;
    const int lane = tid & 31;
    const int w = tid >> 5;
    const int lg = lane >> 2;
    const int lt = lane & 3;
    const int qt = (gridDim.x - 1) - blockIdx.x;   // big CTAs first
    const int h = blockIdx.y;
    const int b = blockIdx.z;
    const int qbase = qt * FQ;
    const size_t head = (size_t)h * DD;

    // stage raw Q (pre-scaled by 1/sqrt(D)=0.125)
    for (int i = tid; i < FQ * 16; i += 256) {
        int row = i >> 4, c4 = (i & 15) * 4;
        float4 q4 = *(const float4*)&Qp[((size_t)(b * SS + qbase + row)) * EE + head + c4];
        q4.x *= 0.125f; q4.y *= 0.125f; q4.z *= 0.125f; q4.w *= 0.125f;
        *(float4*)&Qr[row * QR_STR + c4] = q4;
    }
    __syncthreads();

    // Q fragments split ONCE into registers
    const int r0 = w * 16 + lg;
    uint32_t qh[8][4], ql[8][4];
#pragma unroll
    for (int ks = 0; ks < 8; ks++) {
        const int kk = ks * 8 + lt;
        tf32_split(Qr[r0 * QR_STR + kk],           qh[ks][0], ql[ks][0]);
        tf32_split(Qr[(r0 + 8) * QR_STR + kk],     qh[ks][1], ql[ks][1]);
        tf32_split(Qr[r0 * QR_STR + kk + 4],       qh[ks][2], ql[ks][2]);
        tf32_split(Qr[(r0 + 8) * QR_STR + kk + 4], qh[ks][3], ql[ks][3]);
    }

    float oacc[8][4];
#pragma unroll
    for (int ni = 0; ni < 8; ni++)
#pragma unroll
        for (int r = 0; r < 4; r++) oacc[ni][r] = 0.0f;
    float m0 = -1e30f, m1 = -1e30f, l0 = 0.0f, l1 = 0.0f;

    const int nkt = (qbase + FQ) / FK;   // 2*qt + 2 key tiles

    for (int kt = 0; kt < nkt; kt++) {
        const int kbase = kt * FK;
        __syncthreads();   // prior PV reads of P/V + QK reads of K done
        // load K,V tile; split each element ONCE
        for (int i = tid; i < FK * 16; i += 256) {
            int row = i >> 4, c4 = (i & 15) * 4;
            const size_t g = ((size_t)(b * SS + kbase + row)) * EE + head + c4;
            float4 k4 = *(const float4*)&Kp[g];
            float4 v4 = *(const float4*)&Vp[g];
            uint32_t h0, h1, h2, h3, lo0, lo1, lo2, lo3;
            tf32_split(k4.x, h0, lo0); tf32_split(k4.y, h1, lo1);
            tf32_split(k4.z, h2, lo2); tf32_split(k4.w, h3, lo3);
            *(uint4*)&Khi[row * K_STR + c4] = make_uint4(h0, h1, h2, h3);
            *(uint4*)&Klo[row * K_STR + c4] = make_uint4(lo0, lo1, lo2, lo3);
            tf32_split(v4.x, h0, lo0); tf32_split(v4.y, h1, lo1);
            tf32_split(v4.z, h2, lo2); tf32_split(v4.w, h3, lo3);
            *(uint4*)&Vhi[row * V_STR + c4] = make_uint4(h0, h1, h2, h3);
            *(uint4*)&Vlo[row * V_STR + c4] = make_uint4(lo0, lo1, lo2, lo3);
        }
        __syncthreads();

        // ---- S = Q @ K^T : pure LDS + HMMA
        float sacc[8][4];
#pragma unroll
        for (int ni = 0; ni < 8; ni++)
#pragma unroll
            for (int r = 0; r < 4; r++) sacc[ni][r] = 0.0f;

#pragma unroll
        for (int ks = 0; ks < 8; ks++) {
            const int kk = ks * 8 + lt;
#pragma unroll
            for (int ni = 0; ni < 8; ni++) {
                const int krow = ni * 8 + lg;
                uint32_t bh[2], bl[2];
                bh[0] = __float_as_uint(Khi[krow * K_STR + kk]);
                bh[1] = __float_as_uint(Khi[krow * K_STR + kk + 4]);
                bl[0] = __float_as_uint(Klo[krow * K_STR + kk]);
                bl[1] = __float_as_uint(Klo[krow * K_STR + kk + 4]);
                mma_tf32(sacc[ni], qh[ks], bh);
                mma_tf32(sacc[ni], ql[ks], bh);
                mma_tf32(sacc[ni], qh[ks], bl);
            }
        }

        // ---- causal mask (near-diagonal tiles only)
        if (kt >= 2 * qt) {
            const int grow0 = qbase + r0;
#pragma unroll
            for (int ni = 0; ni < 8; ni++) {
                const int c0 = kbase + ni * 8 + lt * 2;
                if (c0 > grow0)         sacc[ni][0] = -1e30f;
                if (c0 + 1 > grow0)     sacc[ni][1] = -1e30f;
                if (c0 > grow0 + 8)     sacc[ni][2] = -1e30f;
                if (c0 + 1 > grow0 + 8) sacc[ni][3] = -1e30f;
            }
        }

        // ---- online softmax (rows lg, lg+8; quad shfl)
        float rmax0 = -1e30f, rmax1 = -1e30f;
#pragma unroll
        for (int ni = 0; ni < 8; ni++) {
            rmax0 = fmaxf(rmax0, fmaxf(sacc[ni][0], sacc[ni][1]));
            rmax1 = fmaxf(rmax1, fmaxf(sacc[ni][2], sacc[ni][3]));
        }
        rmax0 = fmaxf(rmax0, __shfl_xor_sync(0xffffffffu, rmax0, 1));
        rmax0 = fmaxf(rmax0, __shfl_xor_sync(0xffffffffu, rmax0, 2));
        rmax1 = fmaxf(rmax1, __shfl_xor_sync(0xffffffffu, rmax1, 1));
        rmax1 = fmaxf(rmax1, __shfl_xor_sync(0xffffffffu, rmax1, 2));

        const float newm0 = fmaxf(m0, rmax0);
        const float newm1 = fmaxf(m1, rmax1);
        const float alpha0 = __expf(m0 - newm0);
        const float alpha1 = __expf(m1 - newm1);
        m0 = newm0; m1 = newm1;

        float rsum0 = 0.0f, rsum1 = 0.0f;
#pragma unroll
        for (int ni = 0; ni < 8; ni++) {
            sacc[ni][0] = __expf(sacc[ni][0] - m0);
            sacc[ni][1] = __expf(sacc[ni][1] - m0);
            sacc[ni][2] = __expf(sacc[ni][2] - m1);
            sacc[ni][3] = __expf(sacc[ni][3] - m1);
            rsum0 += sacc[ni][0] + sacc[ni][1];
            rsum1 += sacc[ni][2] + sacc[ni][3];
        }
        rsum0 += __shfl_xor_sync(0xffffffffu, rsum0, 1);
        rsum0 += __shfl_xor_sync(0xffffffffu, rsum0, 2);
        rsum1 += __shfl_xor_sync(0xffffffffu, rsum1, 1);
        rsum1 += __shfl_xor_sync(0xffffffffu, rsum1, 2);
        l0 = l0 * alpha0 + rsum0;
        l1 = l1 * alpha1 + rsum1;

        // rescale O; split P ONCE and store hi/lo
#pragma unroll
        for (int ni = 0; ni < 8; ni++) {
            oacc[ni][0] *= alpha0;
            oacc[ni][1] *= alpha0;
            oacc[ni][2] *= alpha1;
            oacc[ni][3] *= alpha1;
            uint32_t h0, h1, lo0, lo1;
            const int c = ni * 8 + lt * 2;
            tf32_split(sacc[ni][0], h0, lo0);
            tf32_split(sacc[ni][1], h1, lo1);
            *(uint2*)&Phi[r0 * P_STR + c] = make_uint2(h0, h1);
            *(uint2*)&Plo[r0 * P_STR + c] = make_uint2(lo0, lo1);
            tf32_split(sacc[ni][2], h0, lo0);
            tf32_split(sacc[ni][3], h1, lo1);
            *(uint2*)&Phi[(r0 + 8) * P_STR + c] = make_uint2(h0, h1);
            *(uint2*)&Plo[(r0 + 8) * P_STR + c] = make_uint2(lo0, lo1);
        }
        __syncwarp();   // warp reads only its own P rows

        // ---- O += P @ V : pure LDS + HMMA
#pragma unroll
        for (int ks = 0; ks < 8; ks++) {
            const int kk = ks * 8 + lt;
            uint32_t ph[4], pl[4];
            ph[0] = __float_as_uint(Phi[r0 * P_STR + kk]);
            ph[1] = __float_as_uint(Phi[(r0 + 8) * P_STR + kk]);
            ph[2] = __float_as_uint(Phi[r0 * P_STR + kk + 4]);
            ph[3] = __float_as_uint(Phi[(r0 + 8) * P_STR + kk + 4]);
            pl[0] = __float_as_uint(Plo[r0 * P_STR + kk]);
            pl[1] = __float_as_uint(Plo[(r0 + 8) * P_STR + kk]);
            pl[2] = __float_as_uint(Plo[r0 * P_STR + kk + 4]);
            pl[3] = __float_as_uint(Plo[(r0 + 8) * P_STR + kk + 4]);
#pragma unroll
            for (int ni = 0; ni < 8; ni++) {
                const int c = ni * 8 + lg;
                uint32_t bh[2], bl[2];
                bh[0] = __float_as_uint(Vhi[kk * V_STR + c]);
                bh[1] = __float_as_uint(Vhi[(kk + 4) * V_STR + c]);
                bl[0] = __float_as_uint(Vlo[kk * V_STR + c]);
                bl[1] = __float_as_uint(Vlo[(kk + 4) * V_STR + c]);
                mma_tf32(oacc[ni], ph, bh);
                mma_tf32(oacc[ni], pl, bh);
                mma_tf32(oacc[ni], ph, bl);
            }
        }
    }

    // ---- epilogue
    const float inv0 = 1.0f / l0;
    const float inv1 = 1.0f / l1;
    const int grow = qbase + r0;
#pragma unroll
    for (int ni = 0; ni < 8; ni++) {
        const size_t col = head + ni * 8 + lt * 2;
        *(float2*)&Out[((size_t)(b * SS + grow)) * EE + col] =
            make_float2(oacc[ni][0] * inv0, oacc[ni][1] * inv0);
        *(float2*)&Out[((size_t)(b * SS + grow + 8)) * EE + col] =
            make_float2(oacc[ni][2] * inv1, oacc[ni][3] * inv1);
    }
}

// ---------------- launch ----------------------------------------------------
extern "C" void kernel_launch(void* const* d_in, const int* in_sizes, int n_in,
                              void* d_out, int out_size)
{
    const float* q  = (const float*)d_in[0];
    const float* k  = (const float*)d_in[1];
    const float* v  = (const float*)d_in[2];
    const float* Wq = (const float*)d_in[3];
    const float* bq = (const float*)d_in[4];
    const float* Wk = (const float*)d_in[5];
    const float* bk = (const float*)d_in[6];
    const float* Wv = (const float*)d_in[7];
    const float* bv = (const float*)d_in[8];
    const float* Wo = (const float*)d_in[9];
    const float* bo = (const float*)d_in[10];
    float* out = (float*)d_out;

    float* qp; cudaGetSymbolAddress((void**)&qp, g_qp);
    float* kp; cudaGetSymbolAddress((void**)&kp, g_kp);
    float* vp; cudaGetSymbolAddress((void**)&vp, g_vp);
    float* at; cudaGetSymbolAddress((void**)&at, g_at);

    cudaFuncSetAttribute(gemm_tf32_mma,
                         cudaFuncAttributeMaxDynamicSharedMemorySize,
                         GEMM_SMEM_B);
    cudaFuncSetAttribute(flash_mma_kernel,
                         cudaFuncAttributeMaxDynamicSharedMemorySize,
                         FLASH3_SMEM_B);

    dim3 ggrid(EE / 128, MM / 128);   // (8, 32)
    gemm_tf32_mma<<<ggrid, 256, GEMM_SMEM_B>>>(q, Wq, bq, qp);
    gemm_tf32_mma<<<ggrid, 256, GEMM_SMEM_B>>>(k, Wk, bk, kp);
    gemm_tf32_mma<<<ggrid, 256, GEMM_SMEM_B>>>(v, Wv, bv, vp);

    dim3 fa_grid(SS / FQ, HH, BB);    // (16, 16, 2)
    flash_mma_kernel<<<fa_grid, 256, FLASH3_SMEM_B>>>(qp, kp, vp, at);

    gemm_tf32_mma<<<ggrid, 256, GEMM_SMEM_B>>>(at, Wo, bo, out);
}